// round 14
// baseline (speedup 1.0000x reference)
#include <cuda_runtime.h>
#include <cstdint>
#include <math.h>

#define NNI   32
#define CCI   256
#define HWI   1024
#define NPIX  (NNI*HWI)
#define NBORD 124
#define NCHK  36

// ---------------- static device scratch ----------------
__device__ uint32_t           g_X32[2][NPIX*8];     // sign bits, channel-packed per pixel
__device__ uint32_t           g_Wc32[2][CCI*72];    // weights channel-packed [o][k*8+q]
__device__ unsigned long long g_Wp64[2][CCI*NCHK];  // weights patch-flat [o][chunk]
__device__ signed char        g_acc8[2][NNI*CCI*HWI];  // conv outputs / 2 (always even)
__device__ float              g_coef[2*CCI];        // A1,B1

// ---------------- helpers ----------------
__device__ __forceinline__ void border_hw(int b, int& h, int& w){
    if (b < 32)       { h = 0;  w = b; }
    else if (b < 64)  { h = 31; w = b - 32; }
    else              { int r = b - 64; h = 1 + (r >> 1); w = (r & 1) ? 31 : 0; }
}
__device__ __forceinline__ long long wred_ll(long long v){
    for (int d = 16; d; d >>= 1) v += __shfl_down_sync(0xffffffffu, v, d);
    return v;
}
__device__ __forceinline__ double wred_d(double v){
    for (int d = 16; d; d >>= 1) v += __shfl_down_sync(0xffffffffu, v, d);
    return v;
}
__device__ __forceinline__ int wred_i(int v){
    for (int d = 16; d; d >>= 1) v += __shfl_down_sync(0xffffffffu, v, d);
    return v;
}

// validity of the 9 taps folded into the 64-bit chunk mask (closed form)
__device__ __forceinline__ unsigned long long vmask_of(int h, int w, int j){
    const unsigned long long BASE = 0x8040201008040201ull; // bits == 0 mod 9
    int o9 = (64*j) % 9;
    unsigned long long m = 0ull;
    #pragma unroll
    for (int k = 0; k < 9; k++){
        int kh = k/3, kw = k - 3*kh;
        int hh = h + kh - 1, ww = w + kw - 1;
        if ((unsigned)hh < 32u && (unsigned)ww < 32u){
            int r = k - o9; if (r < 0) r += 9;
            m |= BASE << r;
        }
    }
    return m;
}

// ---------------- pack weights + regularizer. grid <<<513,128>>> ----------------
__global__ void k_pack_w(const float* __restrict__ w1, const float* __restrict__ w2,
                         const float* __restrict__ reg0, float* __restrict__ out, int out_size){
    int blk = blockIdx.x, t = threadIdx.x;
    if (blk == 512){
        int cnt = 0;
        for (int i = t; i < HWI*NCHK; i += 128){
            int hw = i / NCHK, j = i - hw*NCHK;
            cnt += (int)(__popcll(vmask_of(hw >> 5, hw & 31, j)) & 1ull);
        }
        __shared__ int sh[4];
        cnt = wred_i(cnt);
        if ((t & 31) == 0) sh[t >> 5] = cnt;
        __syncthreads();
        if (t == 0){
            int T = sh[0] + sh[1] + sh[2] + sh[3];
            out[out_size - 1] = reg0[0] + 3.0f * (float)T / 1024.0f;
        }
        return;
    }
    int which = blk >> 8, o = blk & 255;
    const float* w = which ? w2 : w1;
    if (t < 72){
        int k = t >> 3, q2 = t & 7;
        uint32_t bits = 0;
        for (int b = 0; b < 32; b++){
            int c = q2*32 + b;
            bits |= (uint32_t)(w[(size_t)(o*CCI + c)*9 + k] >= 0.f) << b;
        }
        g_Wc32[which][o*72 + t] = bits;
    } else if (t < 72 + NCHK){
        int j = t - 72;
        unsigned long long bits = 0ull;
        for (int b = 0; b < 64; b++){
            int f = 64*j + b;
            int c = f / 9, k = f - 9*c;
            bits |= (unsigned long long)(w[(size_t)(o*CCI + c)*9 + k] >= 0.f) << b;
        }
        g_Wp64[which][o*NCHK + j] = bits;
    }
}

// ---------------- pack x0: coalesced + ballot + bit transpose. grid <<<1024,256>>> ----------------
__global__ void k_pack_x1(const float* __restrict__ x){
    __shared__ uint32_t sB[256];
    int blk = blockIdx.x;             // n*32 + h
    int n = blk >> 5, h = blk & 31;
    int t = threadIdx.x, warp = t >> 5, lane = t & 31;
    for (int it = 0; it < 32; it++){
        int c = warp*32 + it;
        float v = x[(((size_t)n*CCI + c) << 10) + (h << 5) + lane];
        uint32_t m = __ballot_sync(0xffffffffu, v >= 0.f);
        if (lane == 0) sB[c] = m;
    }
    __syncthreads();
    int p = t & 31, q = t >> 5;
    uint32_t wd = 0;
    #pragma unroll
    for (int b = 0; b < 32; b++) wd |= ((sB[q*32 + b] >> p) & 1u) << b;
    g_X32[0][((size_t)(blk*32 + p))*8 + q] = wd;
}

// ---------------- pack sign(bn1(2*a1)). grid <<<1024,256>>> ----------------
__global__ void k_pack_x2(){
    __shared__ uint32_t sB[256];
    int blk = blockIdx.x;
    int n = blk >> 5, h = blk & 31;
    int t = threadIdx.x, warp = t >> 5, lane = t & 31;
    for (int it = 0; it < 32; it++){
        int c = warp*32 + it;
        float A = g_coef[c], B = g_coef[CCI + c];
        float v = 2.0f * (float)g_acc8[0][(((size_t)n*CCI + c) << 10) + (h << 5) + lane];
        uint32_t m = __ballot_sync(0xffffffffu, (A*v + B) >= 0.f);
        if (lane == 0) sB[c] = m;
    }
    __syncthreads();
    int p = t & 31, q = t >> 5;
    uint32_t wd = 0;
    #pragma unroll
    for (int b = 0; b < 32; b++) wd |= ((sB[q*32 + b] >> p) & 1u) << b;
    g_X32[1][((size_t)(blk*32 + p))*8 + q] = wd;
}

// ---------------- interior conv: XNOR + 3:2 CSA popcount. grid <<<1920,256>>> ----------------
__global__ void __launch_bounds__(256) k_conv_int(int which){
    __shared__ uint32_t sw[128*72];        // 128 output channels' weights
    __shared__ uint32_t sx[8*102];         // [q][kh*34 + col]
    int blk   = blockIdx.x;
    int ohalf = blk & 1;
    int nh    = blk >> 1;
    int n = nh / 30, h = 1 + nh % 30;
    int t = threadIdx.x;

    for (int i = t; i < 128*72; i += 256) sw[i] = g_Wc32[which][ohalf*128*72 + i];
    {
        const uint32_t* base = &g_X32[which][((size_t)(n*32 + (h-1))*32) * 8];
        for (int i = t; i < 768; i += 256){
            int kh = i >> 8, rem = i & 255, col = rem >> 3, q = rem & 7;
            sx[q*102 + kh*34 + col] = base[i];
        }
    }
    __syncthreads();

    int wq = t & 31;
    int og = t >> 5;
    if (wq < 1 || wq > 30) return;

    int mm[16];
    #pragma unroll
    for (int i = 0; i < 16; i++) mm[i] = 0;

    #pragma unroll
    for (int kh = 0; kh < 3; kh++){
        uint32_t xr[24];
        #pragma unroll
        for (int q = 0; q < 8; q++)
            #pragma unroll
            for (int kw = 0; kw < 3; kw++)
                xr[kw*8 + q] = sx[q*102 + kh*34 + (wq - 1 + kw)];
        #pragma unroll
        for (int i = 0; i < 16; i++){
            const uint4* w4 = (const uint4*)&sw[(og*16 + i)*72 + kh*24];
            uint4 v0 = w4[0], v1 = w4[1], v2 = w4[2], v3 = w4[3], v4 = w4[4], v5 = w4[5];
            uint32_t wv[24] = {v0.x,v0.y,v0.z,v0.w, v1.x,v1.y,v1.z,v1.w,
                               v2.x,v2.y,v2.z,v2.w, v3.x,v3.y,v3.z,v3.w,
                               v4.x,v4.y,v4.z,v4.w, v5.x,v5.y,v5.z,v5.w};
            int acc = 0;
            #pragma unroll
            for (int j = 0; j < 8; j++){
                uint32_t a = xr[3*j]     ^ wv[3*j];
                uint32_t b = xr[3*j + 1] ^ wv[3*j + 1];
                uint32_t c = xr[3*j + 2] ^ wv[3*j + 2];
                uint32_t s  = a ^ b ^ c;                     // 1 LOP3
                uint32_t cy = (a & b) | (c & (a | b));       // 1 LOP3
                acc += __popc(s) + 2*__popc(cy);
            }
            mm[i] += acc;
        }
    }

    signed char* dst = &g_acc8[which][(size_t)n*CCI*HWI + h*32 + wq];
    #pragma unroll
    for (int i = 0; i < 16; i++){
        int D = 2304 - 2*mm[i];
        D = D < -254 ? -254 : (D > 254 ? 254 : D);
        int o = ohalf*128 + og*16 + i;
        dst[(size_t)o*HWI] = (signed char)(D >> 1);   // D always even
    }
}

// ---------------- border: fused gather + quantized conv (int8 store). grid <<<3968,256>>> ----------------
__global__ void k_border(int which){
    __shared__ unsigned long long sxp[NCHK], svm[NCHK];
    __shared__ int svc[NCHK];
    int blk = blockIdx.x;
    int n = blk / NBORD, b = blk % NBORD;
    int h, w; border_hw(b, h, w);
    int t = threadIdx.x;

    if (t < NCHK) sxp[t] = 0ull;
    __syncthreads();

    if (t < 144){                      // 4 threads per chunk, 16 bits each
        int j = t >> 2, q = t & 3;
        unsigned long long bits = 0ull;
        for (int bb = q*16; bb < q*16 + 16; bb++){
            int f = 64*j + bb;
            int c = f / 9, k = f - 9*c;
            int kh = k / 3, kw = k % 3;
            int hh = h + kh - 1, ww = w + kw - 1;
            if ((unsigned)hh < 32u && (unsigned)ww < 32u){
                uint32_t word = g_X32[which][(((n*32 + hh)*32 + ww) << 3) + (c >> 5)];
                bits |= (unsigned long long)((word >> (c & 31)) & 1u) << bb;
            }
        }
        atomicOr(&sxp[j], bits);
    } else if (t < 144 + NCHK){
        int j = t - 144;
        unsigned long long m = vmask_of(h, w, j);
        svm[j] = m;
        svc[j] = __popcll(m);
    }
    __syncthreads();

    int o = t;
    const unsigned long long* wp = &g_Wp64[which][o*NCHK];
    int acc = 0;
    #pragma unroll
    for (int j = 0; j < NCHK; j++){
        int mmv = __popcll((sxp[j] ^ wp[j]) & svm[j]);
        int ps = svc[j] - 2*mmv;
        acc += ps + ((ps & 1) ? ((ps & 2) - 1) : 0);
    }
    acc = acc < -254 ? -254 : (acc > 254 ? 254 : acc);
    g_acc8[which][(size_t)(n*CCI + o)*HWI + h*32 + w] = (signed char)(acc >> 1);  // acc even
}

// ---------------- bn1: stats (over v=2a) + coef fused. grid <<<256,512>>> ----------------
__global__ void k_bn1(const float* __restrict__ gamma, const float* __restrict__ beta){
    int c = blockIdx.x, t = threadIdx.x;
    int s = 0, q = 0;
    for (int n = 0; n < NNI; n++){
        const signed char* row = &g_acc8[0][(((size_t)n*CCI + c) << 10) + 2*t];
        int a0 = row[0], a1 = row[1];
        s += a0 + a1; q += a0*a0 + a1*a1;
    }
    __shared__ long long shs[16], shq[16];
    long long sl = wred_ll((long long)s), ql = wred_ll((long long)q);
    if ((t & 31) == 0){ shs[t >> 5] = sl; shq[t >> 5] = ql; }
    __syncthreads();
    if (t == 0){
        long long S = 0, Q = 0;
        for (int i = 0; i < 16; i++){ S += shs[i]; Q += shq[i]; }
        const double Nn = (double)(NNI*HWI);
        double m   = 2.0 * (double)S / Nn;             // v = 2a
        double var = 4.0 * (double)Q / Nn - m*m;
        double A   = (1.0 / sqrt(var + 1e-5)) * (double)gamma[c];
        g_coef[c]       = (float)A;
        g_coef[CCI + c] = (float)((double)beta[c] - m*A);
    }
}

// ---------------- bn2 + final fused: stage f32 y in 128KB smem (single x0 read). grid <<<256,512>>> ----------------
__global__ void k_bn2f(const float* __restrict__ x0,
                       const float* __restrict__ gamma, const float* __restrict__ beta,
                       float* __restrict__ out){
    extern __shared__ float sy[];          // 32768 floats = 128KB
    __shared__ double shs[16], shq[16];
    __shared__ float sAB[2];
    int c = blockIdx.x, t = threadIdx.x;

    double s = 0.0, q = 0.0;
    for (int i = t; i < 16384; i += 512){
        int n = i >> 9, rem = (i & 511) << 1;
        size_t base = (((size_t)n*CCI + c) << 10) + rem;
        const signed char* ap = &g_acc8[1][base];
        float2 xv = *(const float2*)&x0[base];
        float y0 = 2.0f*(float)ap[0] + xv.x;
        float y1 = 2.0f*(float)ap[1] + xv.y;
        *(float2*)&sy[2*i] = make_float2(y0, y1);
        s += (double)y0 + (double)y1;
        q += (double)y0*(double)y0 + (double)y1*(double)y1;
    }
    s = wred_d(s); q = wred_d(q);
    if ((t & 31) == 0){ shs[t >> 5] = s; shq[t >> 5] = q; }
    __syncthreads();
    if (t == 0){
        double S = 0, Q = 0;
        for (int i = 0; i < 16; i++){ S += shs[i]; Q += shq[i]; }
        const double Nn = (double)(NNI*HWI);
        double m   = S / Nn;
        double var = Q / Nn - m*m;
        double A   = (1.0 / sqrt(var + 1e-5)) * (double)gamma[c];
        sAB[0] = (float)A;
        sAB[1] = (float)((double)beta[c] - m*A);
    }
    __syncthreads();
    float A = sAB[0], B = sAB[1];
    for (int i = t; i < 16384; i += 512){
        int n = i >> 9, rem = (i & 511) << 1;
        size_t base = (((size_t)n*CCI + c) << 10) + rem;
        float2 yv = *(const float2*)&sy[2*i];
        float z0 = fminf(1.f, fmaxf(-1.f, A*yv.x + B));
        float z1 = fminf(1.f, fmaxf(-1.f, A*yv.y + B));
        *(float2*)&out[base] = make_float2(z0, z1);
    }
}

// ---------------- launch ----------------
extern "C" void kernel_launch(void* const* d_in, const int* in_sizes, int n_in,
                              void* d_out, int out_size){
    const float* x0     = (const float*)d_in[0];
    const float* reg0   = (const float*)d_in[1];
    const float* w1     = (const float*)d_in[2];
    const float* gamma1 = (const float*)d_in[3];
    const float* beta1  = (const float*)d_in[4];
    const float* w2     = (const float*)d_in[5];
    const float* gamma2 = (const float*)d_in[6];
    const float* beta2  = (const float*)d_in[7];
    float* out = (float*)d_out;

    cudaFuncSetAttribute(k_bn2f, cudaFuncAttributeMaxDynamicSharedMemorySize, 131072);

    k_pack_w<<<513, 128>>>(w1, w2, reg0, out, out_size);   // 0 (weights + regularizer)
    k_pack_x1<<<1024, 256>>>(x0);                          // 1
    k_border<<<NNI*NBORD, 256>>>(0);                       // 2
    k_conv_int<<<NNI*30*2, 256>>>(0);                      // 3  <-- profiled slot
    k_bn1<<<256, 512>>>(gamma1, beta1);                    // 4
    k_pack_x2<<<1024, 256>>>();                            // 5
    k_conv_int<<<NNI*30*2, 256>>>(1);                      // 6
    k_border<<<NNI*NBORD, 256>>>(1);                       // 7
    k_bn2f<<<256, 512, 131072>>>(x0, gamma2, beta2, out);  // 8
}

// round 15
// speedup vs baseline: 1.6628x; 1.6628x over previous
#include <cuda_runtime.h>
#include <cstdint>
#include <math.h>

#define NNI   32
#define CCI   256
#define HWI   1024
#define NPIX  (NNI*HWI)
#define NBORD 124
#define NCHK  36

// ---------------- static device scratch ----------------
__device__ uint32_t           g_X32[2][NPIX*8];     // sign bits, channel-packed per pixel
__device__ uint32_t           g_Wc32[2][CCI*72];    // weights channel-packed [o][k*8+q]
__device__ unsigned long long g_Wp64[2][CCI*NCHK];  // weights patch-flat [o][chunk]
__device__ signed char        g_acc8[2][NNI*CCI*HWI];  // conv outputs / 2 (always even)
__device__ float              g_coef[2*CCI];        // A1,B1

// ---------------- helpers ----------------
__device__ __forceinline__ void border_hw(int b, int& h, int& w){
    if (b < 32)       { h = 0;  w = b; }
    else if (b < 64)  { h = 31; w = b - 32; }
    else              { int r = b - 64; h = 1 + (r >> 1); w = (r & 1) ? 31 : 0; }
}
__device__ __forceinline__ long long wred_ll(long long v){
    for (int d = 16; d; d >>= 1) v += __shfl_down_sync(0xffffffffu, v, d);
    return v;
}
__device__ __forceinline__ double wred_d(double v){
    for (int d = 16; d; d >>= 1) v += __shfl_down_sync(0xffffffffu, v, d);
    return v;
}
__device__ __forceinline__ int wred_i(int v){
    for (int d = 16; d; d >>= 1) v += __shfl_down_sync(0xffffffffu, v, d);
    return v;
}

// validity of the 9 taps folded into the 64-bit chunk mask (closed form)
__device__ __forceinline__ unsigned long long vmask_of(int h, int w, int j){
    const unsigned long long BASE = 0x8040201008040201ull; // bits == 0 mod 9
    int o9 = (64*j) % 9;
    unsigned long long m = 0ull;
    #pragma unroll
    for (int k = 0; k < 9; k++){
        int kh = k/3, kw = k - 3*kh;
        int hh = h + kh - 1, ww = w + kw - 1;
        if ((unsigned)hh < 32u && (unsigned)ww < 32u){
            int r = k - o9; if (r < 0) r += 9;
            m |= BASE << r;
        }
    }
    return m;
}

// 3:2 carry-save compressor on XNOR'd words; accumulates popc(sum), popc(carry)
#define T3(xa,xb,xc,wa,wb,wc) do {                        \
    uint32_t A_ = (xa)^(wa), B_ = (xb)^(wb), C_ = (xc)^(wc); \
    uint32_t S_  = A_ ^ B_ ^ C_;                          \
    uint32_t CY_ = (A_ & B_) | (C_ & (A_ | B_));          \
    pcs += __popc(S_);                                    \
    pcc += __popc(CY_);                                   \
} while(0)

// ---------------- pack weights + regularizer. grid <<<513,128>>> ----------------
__global__ void k_pack_w(const float* __restrict__ w1, const float* __restrict__ w2,
                         const float* __restrict__ reg0, float* __restrict__ out, int out_size){
    int blk = blockIdx.x, t = threadIdx.x;
    if (blk == 512){
        int cnt = 0;
        for (int i = t; i < HWI*NCHK; i += 128){
            int hw = i / NCHK, j = i - hw*NCHK;
            cnt += (int)(__popcll(vmask_of(hw >> 5, hw & 31, j)) & 1ull);
        }
        __shared__ int sh[4];
        cnt = wred_i(cnt);
        if ((t & 31) == 0) sh[t >> 5] = cnt;
        __syncthreads();
        if (t == 0){
            int T = sh[0] + sh[1] + sh[2] + sh[3];
            out[out_size - 1] = reg0[0] + 3.0f * (float)T / 1024.0f;
        }
        return;
    }
    int which = blk >> 8, o = blk & 255;
    const float* w = which ? w2 : w1;
    if (t < 72){
        int k = t >> 3, q2 = t & 7;
        uint32_t bits = 0;
        for (int b = 0; b < 32; b++){
            int c = q2*32 + b;
            bits |= (uint32_t)(w[(size_t)(o*CCI + c)*9 + k] >= 0.f) << b;
        }
        g_Wc32[which][o*72 + t] = bits;
    } else if (t < 72 + NCHK){
        int j = t - 72;
        unsigned long long bits = 0ull;
        for (int b = 0; b < 64; b++){
            int f = 64*j + b;
            int c = f / 9, k = f - 9*c;
            bits |= (unsigned long long)(w[(size_t)(o*CCI + c)*9 + k] >= 0.f) << b;
        }
        g_Wp64[which][o*NCHK + j] = bits;
    }
}

// ---------------- pack x0: coalesced + ballot + bit transpose. grid <<<1024,256>>> ----------------
__global__ void k_pack_x1(const float* __restrict__ x){
    __shared__ uint32_t sB[256];
    int blk = blockIdx.x;             // n*32 + h
    int n = blk >> 5, h = blk & 31;
    int t = threadIdx.x, warp = t >> 5, lane = t & 31;
    for (int it = 0; it < 32; it++){
        int c = warp*32 + it;
        float v = x[(((size_t)n*CCI + c) << 10) + (h << 5) + lane];
        uint32_t m = __ballot_sync(0xffffffffu, v >= 0.f);
        if (lane == 0) sB[c] = m;
    }
    __syncthreads();
    int p = t & 31, q = t >> 5;
    uint32_t wd = 0;
    #pragma unroll
    for (int b = 0; b < 32; b++) wd |= ((sB[q*32 + b] >> p) & 1u) << b;
    g_X32[0][((size_t)(blk*32 + p))*8 + q] = wd;
}

// ---------------- pack sign(bn1(2*a1)). grid <<<1024,256>>> ----------------
__global__ void k_pack_x2(){
    __shared__ uint32_t sB[256];
    int blk = blockIdx.x;
    int n = blk >> 5, h = blk & 31;
    int t = threadIdx.x, warp = t >> 5, lane = t & 31;
    for (int it = 0; it < 32; it++){
        int c = warp*32 + it;
        float A = g_coef[c], B = g_coef[CCI + c];
        float v = 2.0f * (float)g_acc8[0][(((size_t)n*CCI + c) << 10) + (h << 5) + lane];
        uint32_t m = __ballot_sync(0xffffffffu, (A*v + B) >= 0.f);
        if (lane == 0) sB[c] = m;
    }
    __syncthreads();
    int p = t & 31, q = t >> 5;
    uint32_t wd = 0;
    #pragma unroll
    for (int b = 0; b < 32; b++) wd |= ((sB[q*32 + b] >> p) & 1u) << b;
    g_X32[1][((size_t)(blk*32 + p))*8 + q] = wd;
}

// ---------------- interior conv: XNOR + spill-free CSA popcount. grid <<<1920,256>>> ----------------
__global__ void __launch_bounds__(256) k_conv_int(int which){
    __shared__ uint32_t sw[128*72];        // 128 output channels' weights
    __shared__ uint32_t sx[8*102];         // [q][kh*34 + col]
    int blk   = blockIdx.x;
    int ohalf = blk & 1;
    int nh    = blk >> 1;
    int n = nh / 30, h = 1 + nh % 30;
    int t = threadIdx.x;

    for (int i = t; i < 128*72; i += 256) sw[i] = g_Wc32[which][ohalf*128*72 + i];
    {
        const uint32_t* base = &g_X32[which][((size_t)(n*32 + (h-1))*32) * 8];
        for (int i = t; i < 768; i += 256){
            int kh = i >> 8, rem = i & 255, col = rem >> 3, q = rem & 7;
            sx[q*102 + kh*34 + col] = base[i];
        }
    }
    __syncthreads();

    int wq = t & 31;
    int og = t >> 5;
    if (wq < 1 || wq > 30) return;

    int mm[16];
    #pragma unroll
    for (int i = 0; i < 16; i++) mm[i] = 0;

    #pragma unroll
    for (int kh = 0; kh < 3; kh++){
        uint32_t xr[24];
        #pragma unroll
        for (int q = 0; q < 8; q++)
            #pragma unroll
            for (int kw = 0; kw < 3; kw++)
                xr[kw*8 + q] = sx[q*102 + kh*34 + (wq - 1 + kw)];
        #pragma unroll
        for (int i = 0; i < 16; i++){
            const uint4* w4 = (const uint4*)&sw[(og*16 + i)*72 + kh*24];
            uint4 v0 = w4[0], v1 = w4[1], v2 = w4[2], v3 = w4[3], v4 = w4[4], v5 = w4[5];
            int pcs = 0, pcc = 0;
            T3(xr[0], xr[1], xr[2],  v0.x, v0.y, v0.z);
            T3(xr[3], xr[4], xr[5],  v0.w, v1.x, v1.y);
            T3(xr[6], xr[7], xr[8],  v1.z, v1.w, v2.x);
            T3(xr[9], xr[10],xr[11], v2.y, v2.z, v2.w);
            T3(xr[12],xr[13],xr[14], v3.x, v3.y, v3.z);
            T3(xr[15],xr[16],xr[17], v3.w, v4.x, v4.y);
            T3(xr[18],xr[19],xr[20], v4.z, v4.w, v5.x);
            T3(xr[21],xr[22],xr[23], v5.y, v5.z, v5.w);
            mm[i] += pcs + (pcc << 1);
        }
    }

    signed char* dst = &g_acc8[which][(size_t)n*CCI*HWI + h*32 + wq];
    #pragma unroll
    for (int i = 0; i < 16; i++){
        int D = 2304 - 2*mm[i];
        D = D < -254 ? -254 : (D > 254 ? 254 : D);
        int o = ohalf*128 + og*16 + i;
        dst[(size_t)o*HWI] = (signed char)(D >> 1);   // D always even
    }
}

// ---------------- border: fused gather + quantized conv (int8 store). grid <<<3968,256>>> ----------------
__global__ void k_border(int which){
    __shared__ unsigned long long sxp[NCHK], svm[NCHK];
    __shared__ int svc[NCHK];
    int blk = blockIdx.x;
    int n = blk / NBORD, b = blk % NBORD;
    int h, w; border_hw(b, h, w);
    int t = threadIdx.x;

    if (t < NCHK) sxp[t] = 0ull;
    __syncthreads();

    if (t < 144){                      // 4 threads per chunk, 16 bits each
        int j = t >> 2, q = t & 3;
        unsigned long long bits = 0ull;
        for (int bb = q*16; bb < q*16 + 16; bb++){
            int f = 64*j + bb;
            int c = f / 9, k = f - 9*c;
            int kh = k / 3, kw = k % 3;
            int hh = h + kh - 1, ww = w + kw - 1;
            if ((unsigned)hh < 32u && (unsigned)ww < 32u){
                uint32_t word = g_X32[which][(((n*32 + hh)*32 + ww) << 3) + (c >> 5)];
                bits |= (unsigned long long)((word >> (c & 31)) & 1u) << bb;
            }
        }
        atomicOr(&sxp[j], bits);
    } else if (t < 144 + NCHK){
        int j = t - 144;
        unsigned long long m = vmask_of(h, w, j);
        svm[j] = m;
        svc[j] = __popcll(m);
    }
    __syncthreads();

    int o = t;
    const unsigned long long* wp = &g_Wp64[which][o*NCHK];
    int acc = 0;
    #pragma unroll
    for (int j = 0; j < NCHK; j++){
        int mmv = __popcll((sxp[j] ^ wp[j]) & svm[j]);
        int ps = svc[j] - 2*mmv;
        acc += ps + ((ps & 1) ? ((ps & 2) - 1) : 0);
    }
    acc = acc < -254 ? -254 : (acc > 254 ? 254 : acc);
    g_acc8[which][(size_t)(n*CCI + o)*HWI + h*32 + w] = (signed char)(acc >> 1);  // acc even
}

// ---------------- bn1: stats (over v=2a) + coef fused. grid <<<256,512>>> ----------------
__global__ void k_bn1(const float* __restrict__ gamma, const float* __restrict__ beta){
    int c = blockIdx.x, t = threadIdx.x;
    int s = 0, q = 0;
    for (int n = 0; n < NNI; n++){
        const signed char* row = &g_acc8[0][(((size_t)n*CCI + c) << 10) + 2*t];
        int a0 = row[0], a1 = row[1];
        s += a0 + a1; q += a0*a0 + a1*a1;
    }
    __shared__ long long shs[16], shq[16];
    long long sl = wred_ll((long long)s), ql = wred_ll((long long)q);
    if ((t & 31) == 0){ shs[t >> 5] = sl; shq[t >> 5] = ql; }
    __syncthreads();
    if (t == 0){
        long long S = 0, Q = 0;
        for (int i = 0; i < 16; i++){ S += shs[i]; Q += shq[i]; }
        const double Nn = (double)(NNI*HWI);
        double m   = 2.0 * (double)S / Nn;             // v = 2a
        double var = 4.0 * (double)Q / Nn - m*m;
        double A   = (1.0 / sqrt(var + 1e-5)) * (double)gamma[c];
        g_coef[c]       = (float)A;
        g_coef[CCI + c] = (float)((double)beta[c] - m*A);
    }
}

// ---------------- bn2 + final fused: stage int8 a in smem (32KB). grid <<<256,512>>> ----------------
__global__ void k_bn2f(const float* __restrict__ x0,
                       const float* __restrict__ gamma, const float* __restrict__ beta,
                       float* __restrict__ out){
    __shared__ signed char sa[32768];      // acc8 slice for channel c
    __shared__ double shs[16], shq[16];
    __shared__ float sAB[2];
    int c = blockIdx.x, t = threadIdx.x;

    double s = 0.0, q = 0.0;
    for (int i = t; i < 16384; i += 512){
        int n = i >> 9, rem = (i & 511) << 1;
        size_t base = (((size_t)n*CCI + c) << 10) + rem;
        const signed char* ap = &g_acc8[1][base];
        signed char a0 = ap[0], a1 = ap[1];
        float2 xv = *(const float2*)&x0[base];
        float y0 = 2.0f*(float)a0 + xv.x;
        float y1 = 2.0f*(float)a1 + xv.y;
        sa[2*i]     = a0;
        sa[2*i + 1] = a1;
        s += (double)y0 + (double)y1;
        q += (double)y0*(double)y0 + (double)y1*(double)y1;
    }
    s = wred_d(s); q = wred_d(q);
    if ((t & 31) == 0){ shs[t >> 5] = s; shq[t >> 5] = q; }
    __syncthreads();
    if (t == 0){
        double S = 0, Q = 0;
        for (int i = 0; i < 16; i++){ S += shs[i]; Q += shq[i]; }
        const double Nn = (double)(NNI*HWI);
        double m   = S / Nn;
        double var = Q / Nn - m*m;
        double A   = (1.0 / sqrt(var + 1e-5)) * (double)gamma[c];
        sAB[0] = (float)A;
        sAB[1] = (float)((double)beta[c] - m*A);
    }
    __syncthreads();
    float A = sAB[0], B = sAB[1];
    for (int i = t; i < 16384; i += 512){
        int n = i >> 9, rem = (i & 511) << 1;
        size_t base = (((size_t)n*CCI + c) << 10) + rem;
        float2 xv = *(const float2*)&x0[base];     // L2-hot re-read
        float y0 = 2.0f*(float)sa[2*i]     + xv.x;
        float y1 = 2.0f*(float)sa[2*i + 1] + xv.y;
        float z0 = fminf(1.f, fmaxf(-1.f, A*y0 + B));
        float z1 = fminf(1.f, fmaxf(-1.f, A*y1 + B));
        *(float2*)&out[base] = make_float2(z0, z1);
    }
}

// ---------------- launch ----------------
extern "C" void kernel_launch(void* const* d_in, const int* in_sizes, int n_in,
                              void* d_out, int out_size){
    const float* x0     = (const float*)d_in[0];
    const float* reg0   = (const float*)d_in[1];
    const float* w1     = (const float*)d_in[2];
    const float* gamma1 = (const float*)d_in[3];
    const float* beta1  = (const float*)d_in[4];
    const float* w2     = (const float*)d_in[5];
    const float* gamma2 = (const float*)d_in[6];
    const float* beta2  = (const float*)d_in[7];
    float* out = (float*)d_out;

    k_pack_w<<<513, 128>>>(w1, w2, reg0, out, out_size);   // 0 (weights + regularizer)
    k_pack_x1<<<1024, 256>>>(x0);                          // 1
    k_border<<<NNI*NBORD, 256>>>(0);                       // 2
    k_conv_int<<<NNI*30*2, 256>>>(0);                      // 3  <-- profiled slot
    k_bn1<<<256, 512>>>(gamma1, beta1);                    // 4
    k_pack_x2<<<1024, 256>>>();                            // 5
    k_conv_int<<<NNI*30*2, 256>>>(1);                      // 6
    k_border<<<NNI*NBORD, 256>>>(1);                       // 7
    k_bn2f<<<256, 512>>>(x0, gamma2, beta2, out);          // 8
}